// round 3
// baseline (speedup 1.0000x reference)
#include <cuda_runtime.h>
#include <cstdint>

#define B_   1024
#define F_   1024
#define E_   256
#define L1_  16
#define L2C_ 8
#define L3C_ 32
#define NE3_ 128

#define TILE_K 32                 // k-rows per W1 tile (32*256*4B = 32KB, contiguous)
#define NT     (F_ / TILE_K)      // 32 tiles

// Dynamic smem layout (floats):
//   xs   : [8][F_]                         8192 f (32KB)
//   tiles: 2 x [TILE_K][E_]               16384 f (64KB)  (aliased by red after main loop)
//   ht   : [8][E_]                         2048 f (8KB)
//   w2s  : [E_][LOUT]                      E_*LOUT f
#define SM_XS    0
#define SM_TILES (8 * F_)
#define SM_HT    (SM_TILES + 2 * TILE_K * E_)
#define SM_W2    (SM_HT + 8 * E_)
#define SMEM_F(LOUT) (SM_W2 + E_ * (LOUT))
#define SMEM_B(LOUT) (SMEM_F(LOUT) * 4)

// Routing scratch (static device memory — no allocations allowed).
__device__ int g_cnt2[L1_];
__device__ int g_rows2[L1_ * B_];
__device__ int g_cnt3[NE3_];
__device__ int g_rows3[NE3_ * B_];

__global__ void k_zero_counts() {
    int t = threadIdx.x;
    if (t < L1_)  g_cnt2[t] = 0;
    if (t < NE3_) g_cnt3[t] = 0;
}

__device__ __forceinline__ void cp16(float* dst, const float* src) {
    uint32_t d = (uint32_t)__cvta_generic_to_shared(dst);
    asm volatile("cp.async.cg.shared.global [%0], [%1], 16;" :: "r"(d), "l"(src));
}
__device__ __forceinline__ void cp_commit() {
    asm volatile("cp.async.commit_group;");
}
template <int N>
__device__ __forceinline__ void cp_wait() {
    asm volatile("cp.async.wait_group %0;" :: "n"(N));
}

// Unified expert kernel, 512 threads, cp.async double-buffered W1 stream.
// LEVEL=1: dense, expert 0, grid.x = 128 row-chunks of 8.
// LEVEL=2: grid.x = 16 experts, grid.y chunk slots, input 0.6x+0.4y.
// LEVEL=3: grid.x = 128 experts, grid.y chunk slots, input x, no argmax.
template <int LEVEL, int LOUT>
__global__ void __launch_bounds__(512, 1) k_expert(
    const float* __restrict__ x, const float* __restrict__ y,
    const float* __restrict__ W1, const float* __restrict__ gma,
    const float* __restrict__ bta, const float* __restrict__ W2,
    const float* __restrict__ b2, float* __restrict__ out)
{
    extern __shared__ float sm[];
    float* xs    = sm + SM_XS;       // [8][F_]
    float* tiles = sm + SM_TILES;    // 2 x [TILE_K][E_]
    float* ht    = sm + SM_HT;       // [8][E_]
    float* w2s   = sm + SM_W2;       // [E_][LOUT]
    float* red   = tiles;            // alias: [4 ks][8 r][E_] partials

    __shared__ float lrow[8][LOUT];
    __shared__ float redm[8], redr[8];
    __shared__ int rowids[8];

    const int tid = threadIdx.x;
    const int e = (LEVEL == 1) ? 0 : blockIdx.x;
    const int n = (LEVEL == 1) ? B_ : ((LEVEL == 2) ? g_cnt2[e] : g_cnt3[e]);
    const int cstart = (LEVEL == 1) ? blockIdx.x : blockIdx.y;
    const int cstep  = (LEVEL == 1) ? (B_ / 8) : gridDim.y;

    if (cstart * 8 >= n) return;     // no work for this block

    const float* gma_e = gma + e * E_;
    const float* bta_e = bta + e * E_;
    const float* W2_e  = W2 + (size_t)e * E_ * LOUT;
    const float* b2_e  = b2 + e * LOUT;
    const float* Wg    = W1 + (size_t)e * F_ * E_;
    const int outoff = (LEVEL == 1) ? 0
                     : ((LEVEL == 2) ? B_ * L1_ : B_ * (L1_ + L2C_));

    const int ks = tid >> 7;         // k-split 0..3
    const int c2 = tid & 127;        // column pair: cols 2c2, 2c2+1

    // Stage W2 once per block (fire-and-forget).
    #pragma unroll
    for (int i = tid * 4; i < E_ * LOUT; i += 2048)
        cp16(&w2s[i], &W2_e[i]);
    cp_commit();

    for (int c = cstart; c * 8 < n; c += cstep) {
        // --- prefetch tile 0 immediately ---
        {
            const float* src = Wg;
            float* dst = tiles;
            #pragma unroll
            for (int i = tid * 4; i < TILE_K * E_; i += 2048)
                cp16(&dst[i], &src[i]);
            cp_commit();
        }

        // --- fetch row ids for this chunk ---
        if (tid < 8) {
            int rid = -1;
            int j = c * 8 + tid;
            if (j < n) {
                rid = (LEVEL == 1) ? j
                    : ((LEVEL == 2) ? g_rows2[e * B_ + j] : g_rows3[e * B_ + j]);
            }
            rowids[tid] = rid;
        }
        __syncthreads();

        // --- stage input rows in smem (float4, ft = 0.6x+0.4y for L2) ---
        for (int i = tid; i < 8 * (F_ / 4); i += 512) {
            int rr = i >> 8;          // F_/4 == 256
            int f4 = i & 255;
            int row = rowids[rr];
            float4 v = make_float4(0.f, 0.f, 0.f, 0.f);
            if (row >= 0) {
                float4 xv = reinterpret_cast<const float4*>(x)[row * (F_ / 4) + f4];
                if (LEVEL == 2) {
                    float4 yv = reinterpret_cast<const float4*>(y)[row * (F_ / 4) + f4];
                    v = make_float4(0.6f * xv.x + 0.4f * yv.x,
                                    0.6f * xv.y + 0.4f * yv.y,
                                    0.6f * xv.z + 0.4f * yv.z,
                                    0.6f * xv.w + 0.4f * yv.w);
                } else {
                    v = xv;
                }
            }
            reinterpret_cast<float4*>(&xs[rr * F_])[f4] = v;
        }
        __syncthreads();

        // --- main GEMM: double-buffered cp.async W1 stream ---
        float2 acc[8];
        #pragma unroll
        for (int r = 0; r < 8; ++r) acc[r] = make_float2(0.f, 0.f);

        #pragma unroll 1
        for (int t = 0; t < NT; ++t) {
            if (t + 1 < NT) {        // prefetch next tile
                const float* src = Wg + (size_t)(t + 1) * TILE_K * E_;
                float* dst = tiles + ((t + 1) & 1) * (TILE_K * E_);
                #pragma unroll
                for (int i = tid * 4; i < TILE_K * E_; i += 2048)
                    cp16(&dst[i], &src[i]);
                cp_commit();
                cp_wait<1>();        // tile t arrived
            } else {
                cp_wait<0>();
            }
            __syncthreads();

            const float* wt = tiles + (t & 1) * (TILE_K * E_);
            const int kb = t * TILE_K;
            #pragma unroll
            for (int kk = 0; kk < 8; kk += 4) {
                const int k0 = ks * 8 + kk;      // k within tile
                float4 xv[8];
                #pragma unroll
                for (int r = 0; r < 8; ++r)
                    xv[r] = *reinterpret_cast<const float4*>(&xs[r * F_ + kb + k0]);
                #pragma unroll
                for (int j = 0; j < 4; ++j) {
                    float2 w = *reinterpret_cast<const float2*>(&wt[(k0 + j) * E_ + c2 * 2]);
                    #pragma unroll
                    for (int r = 0; r < 8; ++r) {
                        float xvv = (j == 0) ? xv[r].x : (j == 1) ? xv[r].y
                                  : (j == 2) ? xv[r].z : xv[r].w;
                        acc[r].x = fmaf(xvv, w.x, acc[r].x);
                        acc[r].y = fmaf(xvv, w.y, acc[r].y);
                    }
                }
            }
            __syncthreads();         // buffer reuse guard
        }

        // --- k-split reduction via smem (red aliases tiles; all loads done) ---
        #pragma unroll
        for (int r = 0; r < 8; ++r)
            *reinterpret_cast<float2*>(&red[(ks * 8 + r) * E_ + c2 * 2]) = acc[r];
        __syncthreads();
        {
            const float4* r4 = reinterpret_cast<const float4*>(red);
            float4 s = r4[0 * 512 + tid];
            #pragma unroll
            for (int k = 1; k < 4; ++k) {
                float4 p = r4[k * 512 + tid];
                s.x += p.x; s.y += p.y; s.z += p.z; s.w += p.w;
            }
            reinterpret_cast<float4*>(ht)[tid] = s;
        }
        __syncthreads();

        // --- LayerNorm stats: warp w (< 8) reduces row w ---
        if (tid < 256) {
            int w = tid >> 5, lane = tid & 31;
            float s = 0.f, ss = 0.f;
            #pragma unroll
            for (int k = lane; k < E_; k += 32) {
                float v = ht[w * E_ + k];
                s += v; ss += v * v;
            }
            #pragma unroll
            for (int o = 16; o > 0; o >>= 1) {
                s  += __shfl_xor_sync(0xffffffffu, s, o);
                ss += __shfl_xor_sync(0xffffffffu, ss, o);
            }
            if (lane == 0) {
                float m = s * (1.f / E_);
                float var = ss * (1.f / E_) - m * m;
                redm[w] = m;
                redr[w] = rsqrtf(var + 1e-5f);
            }
        }
        __syncthreads();

        // --- normalize + affine + ReLU ---
        {
            int cc = tid & 255;
            int rbase = (tid >> 8) * 4;
            float gv = gma_e[cc], bv = bta_e[cc];
            #pragma unroll
            for (int rr = 0; rr < 4; ++rr) {
                int r = rbase + rr;
                float v = (ht[r * E_ + cc] - redm[r]) * redr[r] * gv + bv;
                ht[r * E_ + cc] = fmaxf(v, 0.f);
            }
        }
        __syncthreads();

        // --- head GEMM from smem: task (r, cc) ---
        if (tid < 8 * LOUT) {
            int r = tid / LOUT, cc = tid % LOUT;
            int row = rowids[r];
            if (row >= 0) {
                float s = b2_e[cc];
                #pragma unroll 8
                for (int k = 0; k < E_; ++k)
                    s = fmaf(ht[r * E_ + k], w2s[k * LOUT + cc], s);
                out[outoff + row * LOUT + cc] = s;
                if (LEVEL != 3) lrow[r][cc] = s;
            }
        }

        // --- argmax + bucket push (levels 1, 2) ---
        if (LEVEL != 3) {
            __syncthreads();
            if (tid < 8) {
                int row = rowids[tid];
                if (row >= 0) {
                    float best = lrow[tid][0];
                    int bi = 0;
                    #pragma unroll
                    for (int cc = 1; cc < LOUT; ++cc) {
                        float v = lrow[tid][cc];
                        if (v > best) { best = v; bi = cc; }
                    }
                    if (LEVEL == 1) {
                        int pos = atomicAdd(&g_cnt2[bi], 1);
                        g_rows2[bi * B_ + pos] = row;
                    } else {
                        int ei = e * L2C_ + bi;
                        int pos = atomicAdd(&g_cnt3[ei], 1);
                        g_rows3[ei * B_ + pos] = row;
                    }
                }
            }
        }
        __syncthreads();   // protect smem before next chunk
    }
}

extern "C" void kernel_launch(void* const* d_in, const int* in_sizes, int n_in,
                              void* d_out, int out_size) {
    const float* x    = (const float*)d_in[0];
    const float* y    = (const float*)d_in[1];
    const float* l1W1 = (const float*)d_in[2];
    const float* l1g  = (const float*)d_in[3];
    const float* l1b  = (const float*)d_in[4];
    const float* l1W2 = (const float*)d_in[5];
    const float* l1b2 = (const float*)d_in[6];
    const float* l2W1 = (const float*)d_in[7];
    const float* l2g  = (const float*)d_in[8];
    const float* l2b  = (const float*)d_in[9];
    const float* l2W2 = (const float*)d_in[10];
    const float* l2b2 = (const float*)d_in[11];
    const float* l3W1 = (const float*)d_in[12];
    const float* l3g  = (const float*)d_in[13];
    const float* l3b  = (const float*)d_in[14];
    const float* l3W2 = (const float*)d_in[15];
    const float* l3b2 = (const float*)d_in[16];
    float* out = (float*)d_out;

    cudaFuncSetAttribute((const void*)k_expert<1, L1_>,
                         cudaFuncAttributeMaxDynamicSharedMemorySize, SMEM_B(L1_));
    cudaFuncSetAttribute((const void*)k_expert<2, L2C_>,
                         cudaFuncAttributeMaxDynamicSharedMemorySize, SMEM_B(L2C_));
    cudaFuncSetAttribute((const void*)k_expert<3, L3C_>,
                         cudaFuncAttributeMaxDynamicSharedMemorySize, SMEM_B(L3C_));

    k_zero_counts<<<1, 256>>>();
    // Level 1: 128 chunks of 8 rows, dense.
    k_expert<1, L1_><<<dim3(128, 1), 512, SMEM_B(L1_)>>>(x, y, l1W1, l1g, l1b, l1W2, l1b2, out);
    // Level 2: 16 experts x 8 chunk slots (stride loop covers skew).
    k_expert<2, L2C_><<<dim3(16, 8), 512, SMEM_B(L2C_)>>>(x, y, l2W1, l2g, l2b, l2W2, l2b2, out);
    // Level 3: 128 experts x 2 chunk slots (stride loop covers skew).
    k_expert<3, L3C_><<<dim3(128, 2), 512, SMEM_B(L3C_)>>>(x, y, l3W1, l3g, l3b, l3W2, l3b2, out);
}

// round 4
// speedup vs baseline: 1.4545x; 1.4545x over previous
#include <cuda_runtime.h>
#include <cstdint>

#define B_   1024
#define F_   1024
#define E_   256
#define L1_  16
#define L2C_ 8
#define L3C_ 32
#define NE3_ 128

// Dynamic smem layout (floats):
//   xs : [8][F_]        8192 f (32KB)
//   red: [4][8][E_]     8192 f (32KB)
//   ht : [8][E_]        2048 f (8KB)
//   w2s: [E_][LOUT]
#define SM_XS   0
#define SM_RED  (8 * F_)
#define SM_HT   (SM_RED + 4 * 8 * E_)
#define SM_W2   (SM_HT + 8 * E_)
#define SMEM_F(LOUT) (SM_W2 + E_ * (LOUT))
#define SMEM_B(LOUT) (SMEM_F(LOUT) * 4)

// Routing scratch (static device memory — no allocations allowed).
__device__ int g_cnt2[L1_];
__device__ int g_rows2[L1_ * B_];
__device__ int g_cnt3[NE3_];
__device__ int g_rows3[NE3_ * B_];

__global__ void k_zero_counts() {
    int t = threadIdx.x;
    if (t < L1_)  g_cnt2[t] = 0;
    if (t < NE3_) g_cnt3[t] = 0;
}

// Unified expert kernel, 512 threads, register-double-buffered weight stream.
// Thread (ks = tid>>7, c2 = tid&127): k-range [256ks, 256ks+256), cols {2c2, 2c2+1}.
// LEVEL=1: dense, expert 0, grid.x = 128 row-chunks of 8.
// LEVEL=2: grid.x = 16 experts, grid.y chunk slots, input 0.6x+0.4y.
// LEVEL=3: grid.x = 128 experts, grid.y chunk slots, input x, no argmax.
template <int LEVEL, int LOUT>
__global__ void __launch_bounds__(512, 1) k_expert(
    const float* __restrict__ x, const float* __restrict__ y,
    const float* __restrict__ W1, const float* __restrict__ gma,
    const float* __restrict__ bta, const float* __restrict__ W2,
    const float* __restrict__ b2, float* __restrict__ out)
{
    extern __shared__ float sm[];
    float* xs  = sm + SM_XS;    // [8][F_]
    float* red = sm + SM_RED;   // [4][8][E_]
    float* ht  = sm + SM_HT;    // [8][E_]
    float* w2s = sm + SM_W2;    // [E_][LOUT]

    __shared__ float lrow[8][LOUT];
    __shared__ float redm[8], redr[8];
    __shared__ int rowids[8];

    const int tid = threadIdx.x;
    const int e = (LEVEL == 1) ? 0 : blockIdx.x;
    const int n = (LEVEL == 1) ? B_ : ((LEVEL == 2) ? g_cnt2[e] : g_cnt3[e]);
    const int cstart = (LEVEL == 1) ? blockIdx.x : blockIdx.y;
    const int cstep  = (LEVEL == 1) ? (B_ / 8) : gridDim.y;

    if (cstart * 8 >= n) return;     // no work for this block

    const float* gma_e = gma + e * E_;
    const float* bta_e = bta + e * E_;
    const float* W2_e  = W2 + (size_t)e * E_ * LOUT;
    const float* b2_e  = b2 + e * LOUT;
    const float* Wg    = W1 + (size_t)e * F_ * E_;
    const int outoff = (LEVEL == 1) ? 0
                     : ((LEVEL == 2) ? B_ * L1_ : B_ * (L1_ + L2C_));

    const int ks = tid >> 7;         // k-split 0..3
    const int c2 = tid & 127;        // column pair

    for (int c = cstart; c * 8 < n; c += cstep) {
        // --- fetch row ids for this chunk ---
        if (tid < 8) {
            int rid = -1;
            int j = c * 8 + tid;
            if (j < n) {
                rid = (LEVEL == 1) ? j
                    : ((LEVEL == 2) ? g_rows2[e * B_ + j] : g_rows3[e * B_ + j]);
            }
            rowids[tid] = rid;
        }
        __syncthreads();

        // --- stage input rows (float4; ft = 0.6x+0.4y for L2) + W2 ---
        for (int i = tid; i < 8 * (F_ / 4); i += 512) {
            int rr = i >> 8;          // F_/4 == 256
            int f4 = i & 255;
            int row = rowids[rr];
            float4 v = make_float4(0.f, 0.f, 0.f, 0.f);
            if (row >= 0) {
                float4 xv = reinterpret_cast<const float4*>(x)[row * (F_ / 4) + f4];
                if (LEVEL == 2) {
                    float4 yv = reinterpret_cast<const float4*>(y)[row * (F_ / 4) + f4];
                    v = make_float4(0.6f * xv.x + 0.4f * yv.x,
                                    0.6f * xv.y + 0.4f * yv.y,
                                    0.6f * xv.z + 0.4f * yv.z,
                                    0.6f * xv.w + 0.4f * yv.w);
                } else {
                    v = xv;
                }
            }
            reinterpret_cast<float4*>(&xs[rr * F_])[f4] = v;
        }
        for (int i = tid * 4; i < E_ * LOUT; i += 2048)
            *reinterpret_cast<float4*>(&w2s[i]) =
                *reinterpret_cast<const float4*>(&W2_e[i]);
        __syncthreads();

        // --- main GEMM: register double-buffered weight stream ---
        float2 acc[8];
        #pragma unroll
        for (int r = 0; r < 8; ++r) acc[r] = make_float2(0.f, 0.f);

        const float* Wp  = Wg + (size_t)(ks * 256) * E_ + c2 * 2;  // k-batch stride 8*E_
        const float* xsb = xs + ks * 256;                           // + r*F_ + k

        float2 wb0[8], wb1[8];
        #pragma unroll
        for (int j = 0; j < 8; ++j)
            wb0[j] = *reinterpret_cast<const float2*>(Wp + (size_t)j * E_);

        #pragma unroll 1
        for (int b = 0; b < 32; b += 2) {
            // prefetch batch b+1 into wb1 (8 independent LDG.64, no consumers yet)
            {
                const float* Wn = Wp + (size_t)((b + 1) * 8) * E_;
                #pragma unroll
                for (int j = 0; j < 8; ++j)
                    wb1[j] = *reinterpret_cast<const float2*>(Wn + (size_t)j * E_);
            }
            // consume batch b from wb0
            #pragma unroll
            for (int j4 = 0; j4 < 2; ++j4) {
                float4 xv[8];
                #pragma unroll
                for (int r = 0; r < 8; ++r)
                    xv[r] = *reinterpret_cast<const float4*>(
                        &xsb[r * F_ + b * 8 + j4 * 4]);
                #pragma unroll
                for (int jj = 0; jj < 4; ++jj) {
                    float2 w = wb0[j4 * 4 + jj];
                    #pragma unroll
                    for (int r = 0; r < 8; ++r) {
                        float xvv = (jj == 0) ? xv[r].x : (jj == 1) ? xv[r].y
                                  : (jj == 2) ? xv[r].z : xv[r].w;
                        acc[r].x = fmaf(xvv, w.x, acc[r].x);
                        acc[r].y = fmaf(xvv, w.y, acc[r].y);
                    }
                }
            }
            // prefetch batch b+2 into wb0
            if (b + 2 < 32) {
                const float* Wn = Wp + (size_t)((b + 2) * 8) * E_;
                #pragma unroll
                for (int j = 0; j < 8; ++j)
                    wb0[j] = *reinterpret_cast<const float2*>(Wn + (size_t)j * E_);
            }
            // consume batch b+1 from wb1
            #pragma unroll
            for (int j4 = 0; j4 < 2; ++j4) {
                float4 xv[8];
                #pragma unroll
                for (int r = 0; r < 8; ++r)
                    xv[r] = *reinterpret_cast<const float4*>(
                        &xsb[r * F_ + (b + 1) * 8 + j4 * 4]);
                #pragma unroll
                for (int jj = 0; jj < 4; ++jj) {
                    float2 w = wb1[j4 * 4 + jj];
                    #pragma unroll
                    for (int r = 0; r < 8; ++r) {
                        float xvv = (jj == 0) ? xv[r].x : (jj == 1) ? xv[r].y
                                  : (jj == 2) ? xv[r].z : xv[r].w;
                        acc[r].x = fmaf(xvv, w.x, acc[r].x);
                        acc[r].y = fmaf(xvv, w.y, acc[r].y);
                    }
                }
            }
        }

        // --- k-split reduction via smem ---
        #pragma unroll
        for (int r = 0; r < 8; ++r)
            *reinterpret_cast<float2*>(&red[(ks * 8 + r) * E_ + c2 * 2]) = acc[r];
        __syncthreads();
        {
            const float4* r4 = reinterpret_cast<const float4*>(red);
            float4 s = r4[0 * 512 + tid];
            #pragma unroll
            for (int k = 1; k < 4; ++k) {
                float4 p = r4[k * 512 + tid];
                s.x += p.x; s.y += p.y; s.z += p.z; s.w += p.w;
            }
            reinterpret_cast<float4*>(ht)[tid] = s;
        }
        __syncthreads();

        // --- LayerNorm stats: warp w (< 8) reduces row w ---
        if (tid < 256) {
            int w = tid >> 5, lane = tid & 31;
            float s = 0.f, ss = 0.f;
            #pragma unroll
            for (int k = lane; k < E_; k += 32) {
                float v = ht[w * E_ + k];
                s += v; ss += v * v;
            }
            #pragma unroll
            for (int o = 16; o > 0; o >>= 1) {
                s  += __shfl_xor_sync(0xffffffffu, s, o);
                ss += __shfl_xor_sync(0xffffffffu, ss, o);
            }
            if (lane == 0) {
                float m = s * (1.f / E_);
                float var = ss * (1.f / E_) - m * m;
                redm[w] = m;
                redr[w] = rsqrtf(var + 1e-5f);
            }
        }
        __syncthreads();

        // --- normalize + affine + ReLU ---
        {
            int cc = tid & 255;
            int rbase = (tid >> 8) * 4;
            float gv = gma_e[cc], bv = bta_e[cc];
            #pragma unroll
            for (int rr = 0; rr < 4; ++rr) {
                int r = rbase + rr;
                float v = (ht[r * E_ + cc] - redm[r]) * redr[r] * gv + bv;
                ht[r * E_ + cc] = fmaxf(v, 0.f);
            }
        }
        __syncthreads();

        // --- head GEMM from smem: task (r, cc) ---
        if (tid < 8 * LOUT) {
            int r = tid / LOUT, cc = tid % LOUT;
            int row = rowids[r];
            if (row >= 0) {
                float s = b2_e[cc];
                #pragma unroll 8
                for (int k = 0; k < E_; ++k)
                    s = fmaf(ht[r * E_ + k], w2s[k * LOUT + cc], s);
                out[outoff + row * LOUT + cc] = s;
                if (LEVEL != 3) lrow[r][cc] = s;
            }
        }

        // --- argmax + bucket push (levels 1, 2) ---
        if (LEVEL != 3) {
            __syncthreads();
            if (tid < 8) {
                int row = rowids[tid];
                if (row >= 0) {
                    float best = lrow[tid][0];
                    int bi = 0;
                    #pragma unroll
                    for (int cc = 1; cc < LOUT; ++cc) {
                        float v = lrow[tid][cc];
                        if (v > best) { best = v; bi = cc; }
                    }
                    if (LEVEL == 1) {
                        int pos = atomicAdd(&g_cnt2[bi], 1);
                        g_rows2[bi * B_ + pos] = row;
                    } else {
                        int ei = e * L2C_ + bi;
                        int pos = atomicAdd(&g_cnt3[ei], 1);
                        g_rows3[ei * B_ + pos] = row;
                    }
                }
            }
        }
        __syncthreads();   // protect smem before next chunk
    }
}

extern "C" void kernel_launch(void* const* d_in, const int* in_sizes, int n_in,
                              void* d_out, int out_size) {
    const float* x    = (const float*)d_in[0];
    const float* y    = (const float*)d_in[1];
    const float* l1W1 = (const float*)d_in[2];
    const float* l1g  = (const float*)d_in[3];
    const float* l1b  = (const float*)d_in[4];
    const float* l1W2 = (const float*)d_in[5];
    const float* l1b2 = (const float*)d_in[6];
    const float* l2W1 = (const float*)d_in[7];
    const float* l2g  = (const float*)d_in[8];
    const float* l2b  = (const float*)d_in[9];
    const float* l2W2 = (const float*)d_in[10];
    const float* l2b2 = (const float*)d_in[11];
    const float* l3W1 = (const float*)d_in[12];
    const float* l3g  = (const float*)d_in[13];
    const float* l3b  = (const float*)d_in[14];
    const float* l3W2 = (const float*)d_in[15];
    const float* l3b2 = (const float*)d_in[16];
    float* out = (float*)d_out;

    cudaFuncSetAttribute((const void*)k_expert<1, L1_>,
                         cudaFuncAttributeMaxDynamicSharedMemorySize, SMEM_B(L1_));
    cudaFuncSetAttribute((const void*)k_expert<2, L2C_>,
                         cudaFuncAttributeMaxDynamicSharedMemorySize, SMEM_B(L2C_));
    cudaFuncSetAttribute((const void*)k_expert<3, L3C_>,
                         cudaFuncAttributeMaxDynamicSharedMemorySize, SMEM_B(L3C_));

    k_zero_counts<<<1, 256>>>();
    // Level 1: 128 chunks of 8 rows, dense.
    k_expert<1, L1_><<<dim3(128, 1), 512, SMEM_B(L1_)>>>(x, y, l1W1, l1g, l1b, l1W2, l1b2, out);
    // Level 2: 16 experts x 8 chunk slots (stride loop covers skew).
    k_expert<2, L2C_><<<dim3(16, 8), 512, SMEM_B(L2C_)>>>(x, y, l2W1, l2g, l2b, l2W2, l2b2, out);
    // Level 3: 128 experts x 2 chunk slots (stride loop covers skew).
    k_expert<3, L3C_><<<dim3(128, 2), 512, SMEM_B(L3C_)>>>(x, y, l3W1, l3g, l3b, l3W2, l3b2, out);
}

// round 5
// speedup vs baseline: 1.5031x; 1.0334x over previous
#include <cuda_runtime.h>
#include <cstdint>

#define B_   1024
#define F_   1024
#define E_   256
#define L1_  16
#define L2C_ 8
#define L3C_ 32
#define NE3_ 128

#define TL_K 16                   // k-rows per tile (16*256*4B = 16KB)
#define NTL  (F_ / TL_K)          // 64 tiles
#define NBUF 4                    // ring depth (3 in flight + 1 consuming)

// Dynamic smem layout (floats):
//   xs   : [8][F_]          8192 f (32KB)
//   tiles: NBUF x [TL_K][E_] 16384 f (64KB)
//   red  : [4][8][E_]       8192 f (32KB)
//   ht   : [8][E_]          2048 f (8KB)
//   w2s  : [E_][LOUT]
#define SM_XS    0
#define SM_TILES (8 * F_)
#define SM_RED   (SM_TILES + NBUF * TL_K * E_)
#define SM_HT    (SM_RED + 4 * 8 * E_)
#define SM_W2    (SM_HT + 8 * E_)
#define SMEM_F(LOUT) (SM_W2 + E_ * (LOUT))
#define SMEM_B(LOUT) (SMEM_F(LOUT) * 4)

// Routing scratch (static device memory — no allocations allowed).
__device__ int g_cnt2[L1_];
__device__ int g_rows2[L1_ * B_];
__device__ int g_cnt3[NE3_];
__device__ int g_rows3[NE3_ * B_];

__global__ void k_zero_counts() {
    int t = threadIdx.x;
    if (t < L1_)  g_cnt2[t] = 0;
    if (t < NE3_) g_cnt3[t] = 0;
}

__device__ __forceinline__ void cp16(float* dst, const float* src) {
    uint32_t d = (uint32_t)__cvta_generic_to_shared(dst);
    asm volatile("cp.async.cg.shared.global [%0], [%1], 16;" :: "r"(d), "l"(src));
}
__device__ __forceinline__ void cp_commit() {
    asm volatile("cp.async.commit_group;");
}
template <int N>
__device__ __forceinline__ void cp_wait() {
    asm volatile("cp.async.wait_group %0;" :: "n"(N) : "memory");
}

// Unified expert kernel, 512 threads, depth-3 cp.async pipelined W1 stream.
// Thread (ks = tid>>7, c2 = tid&127): within each tile handles k-rows
// ks*4..ks*4+3, cols {2c2, 2c2+1}, all 8 chunk rows.
// LEVEL=1: dense, expert 0, grid.x = 128 row-chunks of 8.
// LEVEL=2: grid.x = 16 experts, grid.y chunk slots, input 0.6x+0.4y.
// LEVEL=3: grid.x = 128 experts, grid.y chunk slots, input x, no argmax.
template <int LEVEL, int LOUT>
__global__ void __launch_bounds__(512, 1) k_expert(
    const float* __restrict__ x, const float* __restrict__ y,
    const float* __restrict__ W1, const float* __restrict__ gma,
    const float* __restrict__ bta, const float* __restrict__ W2,
    const float* __restrict__ b2, float* __restrict__ out)
{
    extern __shared__ float sm[];
    float* xs    = sm + SM_XS;     // [8][F_]
    float* tiles = sm + SM_TILES;  // NBUF x [TL_K][E_]
    float* red   = sm + SM_RED;    // [4][8][E_]
    float* ht    = sm + SM_HT;     // [8][E_]
    float* w2s   = sm + SM_W2;     // [E_][LOUT]

    __shared__ float lrow[8][LOUT];
    __shared__ float redm[8], redr[8];
    __shared__ int rowids[8];

    const int tid = threadIdx.x;
    const int e = (LEVEL == 1) ? 0 : blockIdx.x;
    const int n = (LEVEL == 1) ? B_ : ((LEVEL == 2) ? g_cnt2[e] : g_cnt3[e]);
    const int cstart = (LEVEL == 1) ? blockIdx.x : blockIdx.y;
    const int cstep  = (LEVEL == 1) ? (B_ / 8) : gridDim.y;

    if (cstart * 8 >= n) return;     // no work for this block

    const float* gma_e = gma + e * E_;
    const float* bta_e = bta + e * E_;
    const float* W2_e  = W2 + (size_t)e * E_ * LOUT;
    const float* b2_e  = b2 + e * LOUT;
    const float* Wg    = W1 + (size_t)e * F_ * E_;
    const int outoff = (LEVEL == 1) ? 0
                     : ((LEVEL == 2) ? B_ * L1_ : B_ * (L1_ + L2C_));

    const int ks = tid >> 7;         // k-subrange within tile: rows 4ks..4ks+3
    const int c2 = tid & 127;        // column pair

    // Stage W2 once per block (plain loads; first use is behind a barrier).
    for (int i = tid * 4; i < E_ * LOUT; i += 2048)
        *reinterpret_cast<float4*>(&w2s[i]) =
            *reinterpret_cast<const float4*>(&W2_e[i]);

    for (int c = cstart; c * 8 < n; c += cstep) {
        // --- kick off the weight pipeline FIRST (tiles 0..2) ---
        #pragma unroll
        for (int p = 0; p < NBUF - 1; ++p) {
            const float* src = Wg + (size_t)p * (TL_K * E_);
            float* dst = tiles + p * (TL_K * E_);
            cp16(&dst[tid * 4], &src[tid * 4]);
            cp16(&dst[tid * 4 + 2048], &src[tid * 4 + 2048]);
            cp_commit();
        }

        // --- fetch row ids for this chunk ---
        if (tid < 8) {
            int rid = -1;
            int j = c * 8 + tid;
            if (j < n) {
                rid = (LEVEL == 1) ? j
                    : ((LEVEL == 2) ? g_rows2[e * B_ + j] : g_rows3[e * B_ + j]);
            }
            rowids[tid] = rid;
        }
        __syncthreads();

        // --- stage input rows (covers tile-0 latency) ---
        for (int i = tid; i < 8 * (F_ / 4); i += 512) {
            int rr = i >> 8;          // F_/4 == 256
            int f4 = i & 255;
            int row = rowids[rr];
            float4 v = make_float4(0.f, 0.f, 0.f, 0.f);
            if (row >= 0) {
                float4 xv = reinterpret_cast<const float4*>(x)[row * (F_ / 4) + f4];
                if (LEVEL == 2) {
                    float4 yv = reinterpret_cast<const float4*>(y)[row * (F_ / 4) + f4];
                    v = make_float4(0.6f * xv.x + 0.4f * yv.x,
                                    0.6f * xv.y + 0.4f * yv.y,
                                    0.6f * xv.z + 0.4f * yv.z,
                                    0.6f * xv.w + 0.4f * yv.w);
                } else {
                    v = xv;
                }
            }
            reinterpret_cast<float4*>(&xs[rr * F_])[f4] = v;
        }

        // --- main GEMM: pipelined tile consumption ---
        float2 acc[8];
        #pragma unroll
        for (int r = 0; r < 8; ++r) acc[r] = make_float2(0.f, 0.f);

        #pragma unroll 1
        for (int t = 0; t < NTL; ++t) {
            if (t <= NTL - 3)      cp_wait<2>();   // tile t landed
            else if (t == NTL - 2) cp_wait<1>();
            else                   cp_wait<0>();
            __syncthreads();       // publish tile t; buffer (t-1)&3 now free

            if (t + 3 < NTL) {     // issue tile t+3 into freed buffer
                const float* src = Wg + (size_t)(t + 3) * (TL_K * E_);
                float* dst = tiles + ((t + 3) & (NBUF - 1)) * (TL_K * E_);
                cp16(&dst[tid * 4], &src[tid * 4]);
                cp16(&dst[tid * 4 + 2048], &src[tid * 4 + 2048]);
                cp_commit();
            }

            const float* wt = tiles + (t & (NBUF - 1)) * (TL_K * E_);
            const int kb = t * TL_K + ks * 4;      // global k base for this thread
            float4 xv[8];
            #pragma unroll
            for (int r = 0; r < 8; ++r)
                xv[r] = *reinterpret_cast<const float4*>(&xs[r * F_ + kb]);
            #pragma unroll
            for (int j = 0; j < 4; ++j) {
                float2 w = *reinterpret_cast<const float2*>(
                    &wt[(ks * 4 + j) * E_ + c2 * 2]);
                #pragma unroll
                for (int r = 0; r < 8; ++r) {
                    float xvv = (j == 0) ? xv[r].x : (j == 1) ? xv[r].y
                              : (j == 2) ? xv[r].z : xv[r].w;
                    acc[r].x = fmaf(xvv, w.x, acc[r].x);
                    acc[r].y = fmaf(xvv, w.y, acc[r].y);
                }
            }
        }
        __syncthreads();

        // --- k-split reduction via smem ---
        #pragma unroll
        for (int r = 0; r < 8; ++r)
            *reinterpret_cast<float2*>(&red[(ks * 8 + r) * E_ + c2 * 2]) = acc[r];
        __syncthreads();
        {
            const float4* r4 = reinterpret_cast<const float4*>(red);
            float4 s = r4[0 * 512 + tid];
            #pragma unroll
            for (int k = 1; k < 4; ++k) {
                float4 p = r4[k * 512 + tid];
                s.x += p.x; s.y += p.y; s.z += p.z; s.w += p.w;
            }
            reinterpret_cast<float4*>(ht)[tid] = s;
        }
        __syncthreads();

        // --- LayerNorm stats: warp w (< 8) reduces row w ---
        if (tid < 256) {
            int w = tid >> 5, lane = tid & 31;
            float s = 0.f, ss = 0.f;
            #pragma unroll
            for (int k = lane; k < E_; k += 32) {
                float v = ht[w * E_ + k];
                s += v; ss += v * v;
            }
            #pragma unroll
            for (int o = 16; o > 0; o >>= 1) {
                s  += __shfl_xor_sync(0xffffffffu, s, o);
                ss += __shfl_xor_sync(0xffffffffu, ss, o);
            }
            if (lane == 0) {
                float m = s * (1.f / E_);
                float var = ss * (1.f / E_) - m * m;
                redm[w] = m;
                redr[w] = rsqrtf(var + 1e-5f);
            }
        }
        __syncthreads();

        // --- normalize + affine + ReLU ---
        {
            int cc = tid & 255;
            int rbase = (tid >> 8) * 4;
            float gv = gma_e[cc], bv = bta_e[cc];
            #pragma unroll
            for (int rr = 0; rr < 4; ++rr) {
                int r = rbase + rr;
                float v = (ht[r * E_ + cc] - redm[r]) * redr[r] * gv + bv;
                ht[r * E_ + cc] = fmaxf(v, 0.f);
            }
        }
        __syncthreads();

        // --- head GEMM from smem: task (r, cc) ---
        if (tid < 8 * LOUT) {
            int r = tid / LOUT, cc = tid % LOUT;
            int row = rowids[r];
            if (row >= 0) {
                float s = b2_e[cc];
                #pragma unroll 8
                for (int k = 0; k < E_; ++k)
                    s = fmaf(ht[r * E_ + k], w2s[k * LOUT + cc], s);
                out[outoff + row * LOUT + cc] = s;
                if (LEVEL != 3) lrow[r][cc] = s;
            }
        }

        // --- argmax + bucket push (levels 1, 2) ---
        if (LEVEL != 3) {
            __syncthreads();
            if (tid < 8) {
                int row = rowids[tid];
                if (row >= 0) {
                    float best = lrow[tid][0];
                    int bi = 0;
                    #pragma unroll
                    for (int cc = 1; cc < LOUT; ++cc) {
                        float v = lrow[tid][cc];
                        if (v > best) { best = v; bi = cc; }
                    }
                    if (LEVEL == 1) {
                        int pos = atomicAdd(&g_cnt2[bi], 1);
                        g_rows2[bi * B_ + pos] = row;
                    } else {
                        int ei = e * L2C_ + bi;
                        int pos = atomicAdd(&g_cnt3[ei], 1);
                        g_rows3[ei * B_ + pos] = row;
                    }
                }
            }
        }
        __syncthreads();   // protect smem before next chunk
    }
}

extern "C" void kernel_launch(void* const* d_in, const int* in_sizes, int n_in,
                              void* d_out, int out_size) {
    const float* x    = (const float*)d_in[0];
    const float* y    = (const float*)d_in[1];
    const float* l1W1 = (const float*)d_in[2];
    const float* l1g  = (const float*)d_in[3];
    const float* l1b  = (const float*)d_in[4];
    const float* l1W2 = (const float*)d_in[5];
    const float* l1b2 = (const float*)d_in[6];
    const float* l2W1 = (const float*)d_in[7];
    const float* l2g  = (const float*)d_in[8];
    const float* l2b  = (const float*)d_in[9];
    const float* l2W2 = (const float*)d_in[10];
    const float* l2b2 = (const float*)d_in[11];
    const float* l3W1 = (const float*)d_in[12];
    const float* l3g  = (const float*)d_in[13];
    const float* l3b  = (const float*)d_in[14];
    const float* l3W2 = (const float*)d_in[15];
    const float* l3b2 = (const float*)d_in[16];
    float* out = (float*)d_out;

    cudaFuncSetAttribute((const void*)k_expert<1, L1_>,
                         cudaFuncAttributeMaxDynamicSharedMemorySize, SMEM_B(L1_));
    cudaFuncSetAttribute((const void*)k_expert<2, L2C_>,
                         cudaFuncAttributeMaxDynamicSharedMemorySize, SMEM_B(L2C_));
    cudaFuncSetAttribute((const void*)k_expert<3, L3C_>,
                         cudaFuncAttributeMaxDynamicSharedMemorySize, SMEM_B(L3C_));

    k_zero_counts<<<1, 256>>>();
    // Level 1: 128 chunks of 8 rows, dense.
    k_expert<1, L1_><<<dim3(128, 1), 512, SMEM_B(L1_)>>>(x, y, l1W1, l1g, l1b, l1W2, l1b2, out);
    // Level 2: 16 experts x 16 chunk slots (chunks run in parallel blocks).
    k_expert<2, L2C_><<<dim3(16, 16), 512, SMEM_B(L2C_)>>>(x, y, l2W1, l2g, l2b, l2W2, l2b2, out);
    // Level 3: 128 experts x 4 chunk slots (chunks run in parallel blocks).
    k_expert<3, L3C_><<<dim3(128, 4), 512, SMEM_B(L3C_)>>>(x, y, l3W1, l3g, l3b, l3W2, l3b2, out);
}

// round 7
// speedup vs baseline: 3.0690x; 2.0418x over previous
#include <cuda_runtime.h>
#include <cstdint>

#define B_   1024
#define F_   1024
#define E_   256
#define L1_  16
#define L2C_ 8
#define L3C_ 32
#define NE3_ 128

#define ROWS 16                   // rows per chunk
#define NSL  8                    // k-slices per chunk
#define SL_K (F_ / NSL)           // 128

#define MAXCHK 192                // >= 64 + 128 (worst-case L3 chunk count)

// Routing + scheduling + partial scratch (static device memory).
__device__ int g_cnt2[L1_];
__device__ int g_rows2[L1_ * B_];
__device__ int g_cnt3[NE3_];
__device__ int g_rows3[NE3_ * B_];
__device__ int g_chk_e[MAXCHK];
__device__ int g_chk_off[MAXCHK];
__device__ int g_nchk;
// partials: [chunk][slice][row ROWS][col E_]
__device__ float g_part[MAXCHK * NSL * ROWS * E_];

__global__ void k_zero_counts() {
    int t = threadIdx.x;
    if (t < L1_)  g_cnt2[t] = 0;
    if (t < NE3_) g_cnt3[t] = 0;
}

// Build compacted chunk table from per-expert counts. Single thread; <=192 iters.
template <int NEXP>
__global__ void k_sched(const int* __restrict__ cnts) {
    if (threadIdx.x == 0) {
        int t = 0;
        for (int e = 0; e < NEXP; ++e) {
            int cnt = cnts[e];
            for (int off = 0; off < cnt; off += ROWS) {
                g_chk_e[t] = e;
                g_chk_off[t] = off;
                ++t;
            }
        }
        g_nchk = t;
    }
}

// ---------------- GEMM pass: block = (chunk slot, k-slice) ------------------
// 256 threads; thread owns output column `tid`; 16 rows; 128 k.
template <int LEVEL>
__global__ void __launch_bounds__(256, 4) k_gemm(
    const float* __restrict__ x, const float* __restrict__ y,
    const float* __restrict__ W1)
{
    __shared__ __align__(16) float xs[ROWS][SL_K];   // 8KB
    __shared__ int rowids[ROWS];

    const int tid = threadIdx.x;
    const int b = blockIdx.x;     // chunk slot
    const int s = blockIdx.y;     // k-slice

    int e, off, cnt;
    if (LEVEL == 1) {
        e = 0; off = b * ROWS; cnt = B_;
    } else {
        if (b >= g_nchk) return;
        e = g_chk_e[b];
        off = g_chk_off[b];
        cnt = (LEVEL == 2) ? g_cnt2[e] : g_cnt3[e];
    }

    if (tid < ROWS) {
        int rid = -1;
        int j = off + tid;
        if (j < cnt) {
            rid = (LEVEL == 1) ? j
                : ((LEVEL == 2) ? g_rows2[e * B_ + j] : g_rows3[e * B_ + j]);
        }
        rowids[tid] = rid;
    }
    __syncthreads();

    // stage k-slice of 16 input rows (16 x 32 float4)
    for (int i = tid; i < ROWS * (SL_K / 4); i += 256) {
        int rr = i >> 5;          // SL_K/4 == 32
        int f4 = i & 31;
        int row = rowids[rr];
        float4 v = make_float4(0.f, 0.f, 0.f, 0.f);
        if (row >= 0) {
            float4 xv = reinterpret_cast<const float4*>(x)[row * (F_ / 4) + s * 32 + f4];
            if (LEVEL == 2) {
                float4 yv = reinterpret_cast<const float4*>(y)[row * (F_ / 4) + s * 32 + f4];
                v = make_float4(0.6f * xv.x + 0.4f * yv.x,
                                0.6f * xv.y + 0.4f * yv.y,
                                0.6f * xv.z + 0.4f * yv.z,
                                0.6f * xv.w + 0.4f * yv.w);
            } else {
                v = xv;
            }
        }
        reinterpret_cast<float4*>(&xs[rr][0])[f4] = v;
    }
    __syncthreads();

    // GEMM: 128 k x 16 rows for column `tid`; 16 coalesced LDG.32 in flight
    float acc[ROWS];
    #pragma unroll
    for (int r = 0; r < ROWS; ++r) acc[r] = 0.f;

    const float* Wp = W1 + ((size_t)e * F_ + (size_t)s * SL_K) * E_ + tid;

    #pragma unroll 1
    for (int kb = 0; kb < SL_K; kb += 16) {
        float w[16];
        #pragma unroll
        for (int j = 0; j < 16; ++j)
            w[j] = Wp[(size_t)(kb + j) * E_];
        #pragma unroll
        for (int j4 = 0; j4 < 4; ++j4) {
            #pragma unroll
            for (int r = 0; r < ROWS; ++r) {
                float4 xv = *reinterpret_cast<const float4*>(&xs[r][kb + j4 * 4]);
                acc[r] = fmaf(xv.x, w[j4 * 4],     acc[r]);
                acc[r] = fmaf(xv.y, w[j4 * 4 + 1], acc[r]);
                acc[r] = fmaf(xv.z, w[j4 * 4 + 2], acc[r]);
                acc[r] = fmaf(xv.w, w[j4 * 4 + 3], acc[r]);
            }
        }
    }

    // write partials (coalesced)
    float* dst = g_part + ((size_t)(b * NSL + s) * ROWS) * E_ + tid;
    #pragma unroll
    for (int r = 0; r < ROWS; ++r)
        dst[r * E_] = acc[r];
}

// ---------------- Epilogue pass: block = (chunk slot, 8-row group) ----------
// Reduce 8 slice-partials, LayerNorm+ReLU, head GEMM, argmax + bucket push.
template <int LEVEL, int LOUT>
__global__ void __launch_bounds__(256) k_epi(
    const float* __restrict__ gma, const float* __restrict__ bta,
    const float* __restrict__ W2, const float* __restrict__ b2,
    float* __restrict__ out)
{
    __shared__ float ht[8][E_];          // 8KB
    __shared__ float w2s[E_ * LOUT];     // <= 32KB
    __shared__ float lrow[8][LOUT];
    __shared__ float redm[8], redr[8];
    __shared__ int rowids[8];

    const int tid = threadIdx.x;
    const int b = blockIdx.x;            // chunk slot
    const int g = blockIdx.y;            // 8-row group within 16-row chunk

    int e, off, cnt;
    if (LEVEL == 1) {
        e = 0; off = b * ROWS; cnt = B_;
    } else {
        if (b >= g_nchk) return;
        e = g_chk_e[b];
        off = g_chk_off[b];
        cnt = (LEVEL == 2) ? g_cnt2[e] : g_cnt3[e];
    }
    if (off + g * 8 >= cnt) return;      // empty group

    const float* W2_e = W2 + (size_t)e * E_ * LOUT;
    const int outoff = (LEVEL == 1) ? 0
                     : ((LEVEL == 2) ? B_ * L1_ : B_ * (L1_ + L2C_));

    if (tid < 8) {
        int rid = -1;
        int j = off + g * 8 + tid;
        if (j < cnt) {
            rid = (LEVEL == 1) ? j
                : ((LEVEL == 2) ? g_rows2[e * B_ + j] : g_rows3[e * B_ + j]);
        }
        rowids[tid] = rid;
    }

    // reduce partials: thread owns column tid (fixed order -> deterministic)
    {
        const float* base = g_part + (size_t)b * NSL * ROWS * E_ + (g * 8) * E_ + tid;
        #pragma unroll
        for (int r = 0; r < 8; ++r) {
            float sacc = 0.f;
            #pragma unroll
            for (int sl = 0; sl < NSL; ++sl)
                sacc += base[(sl * ROWS + r) * E_];
            ht[r][tid] = sacc;
        }
    }
    // stage W2
    for (int i = tid * 4; i < E_ * LOUT; i += 1024)
        *reinterpret_cast<float4*>(&w2s[i]) =
            *reinterpret_cast<const float4*>(&W2_e[i]);
    __syncthreads();

    // LayerNorm stats: warp w reduces row w
    {
        int w = tid >> 5, lane = tid & 31;
        float sv = 0.f, ss = 0.f;
        #pragma unroll
        for (int k = lane; k < E_; k += 32) {
            float v = ht[w][k];
            sv += v; ss += v * v;
        }
        #pragma unroll
        for (int o = 16; o > 0; o >>= 1) {
            sv += __shfl_xor_sync(0xffffffffu, sv, o);
            ss += __shfl_xor_sync(0xffffffffu, ss, o);
        }
        if (lane == 0) {
            float m = sv * (1.f / E_);
            float var = ss * (1.f / E_) - m * m;
            redm[w] = m;
            redr[w] = rsqrtf(var + 1e-5f);
        }
    }
    __syncthreads();

    // normalize + affine + ReLU
    {
        float gv = gma[e * E_ + tid], bv = bta[e * E_ + tid];
        #pragma unroll
        for (int r = 0; r < 8; ++r) {
            float v = (ht[r][tid] - redm[r]) * redr[r] * gv + bv;
            ht[r][tid] = fmaxf(v, 0.f);
        }
    }
    __syncthreads();

    // head GEMM: task (r, cc)
    if (tid < 8 * LOUT) {
        int r = tid / LOUT, cc = tid % LOUT;
        int row = rowids[r];
        if (row >= 0) {
            float sv = b2[e * LOUT + cc];
            #pragma unroll 8
            for (int k = 0; k < E_; ++k)
                sv = fmaf(ht[r][k], w2s[k * LOUT + cc], sv);
            out[outoff + row * LOUT + cc] = sv;
            if (LEVEL != 3) lrow[r][cc] = sv;
        }
    }

    // argmax + bucket push (levels 1, 2); first-max semantics
    if (LEVEL != 3) {
        __syncthreads();
        if (tid < 8) {
            int row = rowids[tid];
            if (row >= 0) {
                float best = lrow[tid][0];
                int bi = 0;
                #pragma unroll
                for (int cc = 1; cc < LOUT; ++cc) {
                    float v = lrow[tid][cc];
                    if (v > best) { best = v; bi = cc; }
                }
                if (LEVEL == 1) {
                    int pos = atomicAdd(&g_cnt2[bi], 1);
                    g_rows2[bi * B_ + pos] = row;
                } else {
                    int ei = e * L2C_ + bi;
                    int pos = atomicAdd(&g_cnt3[ei], 1);
                    g_rows3[ei * B_ + pos] = row;
                }
            }
        }
    }
}

extern "C" void kernel_launch(void* const* d_in, const int* in_sizes, int n_in,
                              void* d_out, int out_size) {
    const float* x    = (const float*)d_in[0];
    const float* y    = (const float*)d_in[1];
    const float* l1W1 = (const float*)d_in[2];
    const float* l1g  = (const float*)d_in[3];
    const float* l1b  = (const float*)d_in[4];
    const float* l1W2 = (const float*)d_in[5];
    const float* l1b2 = (const float*)d_in[6];
    const float* l2W1 = (const float*)d_in[7];
    const float* l2g  = (const float*)d_in[8];
    const float* l2b  = (const float*)d_in[9];
    const float* l2W2 = (const float*)d_in[10];
    const float* l2b2 = (const float*)d_in[11];
    const float* l3W1 = (const float*)d_in[12];
    const float* l3g  = (const float*)d_in[13];
    const float* l3b  = (const float*)d_in[14];
    const float* l3W2 = (const float*)d_in[15];
    const float* l3b2 = (const float*)d_in[16];
    float* out = (float*)d_out;

    int* d_cnt2 = nullptr;
    int* d_cnt3 = nullptr;
    cudaGetSymbolAddress((void**)&d_cnt2, g_cnt2);
    cudaGetSymbolAddress((void**)&d_cnt3, g_cnt3);

    k_zero_counts<<<1, 256>>>();

    // Level 1: dense, 64 chunks of 16 rows x 8 k-slices; epi on 128 8-row groups.
    k_gemm<1><<<dim3(64, NSL), 256>>>(x, y, l1W1);
    k_epi <1, L1_><<<dim3(64, 2), 256>>>(l1g, l1b, l1W2, l1b2, out);

    // Level 2: chunk table (<= 80 chunks), grid sized for worst case.
    k_sched<L1_><<<1, 32>>>(d_cnt2);
    k_gemm<2><<<dim3(80, NSL), 256>>>(x, y, l2W1);
    k_epi <2, L2C_><<<dim3(80, 2), 256>>>(l2g, l2b, l2W2, l2b2, out);

    // Level 3: chunk table (<= 192 chunks).
    k_sched<NE3_><<<1, 32>>>(d_cnt3);
    k_gemm<3><<<dim3(MAXCHK, NSL), 256>>>(x, y, l3W1);
    k_epi <3, L3C_><<<dim3(MAXCHK, 2), 256>>>(l3g, l3b, l3W2, l3b2, out);
}